// round 9
// baseline (speedup 1.0000x reference)
#include <cuda_runtime.h>
#include <cuda_bf16.h>
#include <cstdint>
#include <math.h>

#define LC   2048
#define CINV 0.35355339059327373f   // 1/(2*sqrt(2))

// Transposed wavelet weights, bf16: [which][k][i*64+o]
__device__ __nv_bfloat16 g_wt[2][(size_t)LC * 4096];

__device__ __forceinline__ float gelu_tanh(float v) {
    float z = 0.7978845608028654f * (v + 0.044715f * v * v * v);
    float t;
    asm("tanh.approx.f32 %0, %1;" : "=f"(t) : "f"(z));
    return 0.5f * v * (1.0f + t);
}

// ---------------------------------------------------------------------------
// Kernel 1: transpose w_approx / w_detail (i,o,l) -> (l, i*64+o), f32 -> bf16
// ---------------------------------------------------------------------------
__global__ void transpose_w_kernel(const float* __restrict__ wA,
                                   const float* __restrict__ wD) {
    __shared__ float tile[32][33];
    const float* src = (blockIdx.z == 0) ? wA : wD;
    __nv_bfloat16* dst = g_wt[blockIdx.z];
    int lbase  = blockIdx.x * 32;
    int iobase = blockIdx.y * 32;
    int tx = threadIdx.x, ty = threadIdx.y;   // block (32, 8)
#pragma unroll
    for (int r = 0; r < 32; r += 8)
        tile[ty + r][tx] = src[(size_t)(iobase + ty + r) * LC + (lbase + tx)];
    __syncthreads();
#pragma unroll
    for (int r = 0; r < 32; r += 8)
        dst[(size_t)(lbase + ty + r) * 4096 + (iobase + tx)] =
            __float2bfloat16(tile[tx][ty + r]);
}

// ---------------------------------------------------------------------------
// Kernel 2: fully fused. Grid 8192 = (k, quarter). 256 threads, 8 batches
// x 8 rows x 64 ch per block. 4 CTAs/SM -> 32 warps.
// smem = 41984 B. shrW dual-use: bf16 W_t then f32 (W_skip+I).
// ---------------------------------------------------------------------------
__global__ __launch_bounds__(256, 4) void fused_kernel(
    const float* __restrict__ x, const float* __restrict__ Ws,
    const float* __restrict__ bsk, float* __restrict__ out)
{
    extern __shared__ float sm[];
    float* xs   = sm;            // 8 b * 520 (8x64 + pad 8)    = 4160 fl
    float* shrW = sm + 4160;     // 4096 fl: bf16 W_t[2][4096] then f32 wsk
    float* uv   = sm + 8256;     // [2][64 i][9]                = 1152 fl
    float* corr = sm + 9408;     // [2][8 b][64 o]              = 1024 fl
    float* bias = sm + 10432;    // 64 fl   (total 10496 fl = 41984 B)

    const int k   = blockIdx.x >> 2;
    const int q   = blockIdx.x & 3;      // batch quarter: batches q*8..q*8+7
    const int tid = threadIdx.x;

    // ---- Phase 0: loads ----
    const float4* x4  = (const float4*)x;
    float4*       xs4 = (float4*)xs;
#pragma unroll
    for (int it = 0; it < 4; it++) {
        int idx = tid + it * 256;           // 0..1023 float4s
        int bl = idx >> 7, r = idx & 127;
        int b  = q * 8 + bl;
        xs4[bl * 130 + r] = x4[(size_t)b * 262144 + (size_t)k * 128 + r];
    }
    {
        const uint4* wt0 = (const uint4*)(g_wt[0] + (size_t)k * 4096);
        const uint4* wt1 = (const uint4*)(g_wt[1] + (size_t)k * 4096);
        uint4* dstw = (uint4*)shrW;
        dstw[tid]       = wt0[tid];         // 512 uint4 per which
        dstw[512 + tid] = wt1[tid];
        if (tid < 256) { }                  // (256 threads cover 0..255; need 512)
        dstw[tid + 256]       = wt0[tid + 256];
        dstw[512 + tid + 256] = wt1[tid + 256];
    }
    if (tid < 64) bias[tid] = bsk[tid];
    __syncthreads();

    // ---- Phase 1: u/v.  p -> (which, bl, i); consecutive tid = consecutive i.
#pragma unroll
    for (int it = 0; it < 4; it++) {
        int p = tid + it * 256;             // 0..1023
        int i = p & 63, bl = (p >> 6) & 7, which = p >> 9;
        const float* xb = xs + bl * 520 + i;
        float e = 0.f, d = 0.f;
#pragma unroll
        for (int j = 0; j < 4; j++) { e += xb[j * 64]; d += xb[(j + 4) * 64]; }
        uv[which * 576 + i * 9 + bl] = (which == 0) ? CINV * (e + d)
                                                    : CINV * (e - d);
    }
    __syncthreads();

    // ---- Phase 2: corrections. thread -> (which, bl, 4 outputs og..og+3)
    {
        const int which = tid >> 7;
        const int r  = tid & 127;
        const int bl = r >> 4;
        const int og = (r & 15) * 4;
        const __nv_bfloat16* W = (const __nv_bfloat16*)shrW + which * 4096;
        const float* U = uv + which * 576;

        float acc0 = 0.f, acc1 = 0.f, acc2 = 0.f, acc3 = 0.f;
#pragma unroll 8
        for (int i = 0; i < 64; i++) {
            float u = U[i * 9 + bl];
            uint2 wv = *(const uint2*)(W + i * 64 + og);   // 4 bf16
            float2 w0 = __bfloat1622float2(*(const __nv_bfloat162*)&wv.x);
            float2 w1 = __bfloat1622float2(*(const __nv_bfloat162*)&wv.y);
            acc0 = fmaf(u, w0.x, acc0);
            acc1 = fmaf(u, w0.y, acc1);
            acc2 = fmaf(u, w1.x, acc2);
            acc3 = fmaf(u, w1.y, acc3);
        }
        float* cp = corr + which * 512 + bl * 64 + og;
        cp[0] = CINV * (acc0 - U[(og + 0) * 9 + bl]);
        cp[1] = CINV * (acc1 - U[(og + 1) * 9 + bl]);
        cp[2] = CINV * (acc2 - U[(og + 2) * 9 + bl]);
        cp[3] = CINV * (acc3 - U[(og + 3) * 9 + bl]);
    }
    __syncthreads();

    // ---- Phase 3: overwrite shrW with (W_skip + I) as f32 ----
#pragma unroll
    for (int it = 0; it < 16; it++) {
        int i = tid + it * 256;             // 0..4095
        float v = Ws[i];
        if ((i >> 6) == (i & 63)) v += 1.0f;
        shrW[i] = v;
    }
    __syncthreads();

    // ---- Phase 4: GEMM + epilogue. thread = (b, rowhalf, 4 cols) ----
    const int b  = tid >> 5;                // 0..7 (== warp id)
    const int rh = (tid >> 4) & 1;          // row half: rows rh*4..rh*4+3
    const int cg = (tid & 15) << 2;
    const float* xb = xs + b * 520 + rh * 4 * 64;

    float acc[4][4] = {};
#pragma unroll 8
    for (int kk = 0; kk < 64; kk += 2) {
        float4 w0 = *(const float4*)(shrW + kk * 64 + cg);
        float4 w1 = *(const float4*)(shrW + (kk + 1) * 64 + cg);
        float2 xv[4];
#pragma unroll
        for (int j = 0; j < 4; j++)
            xv[j] = *(const float2*)(xb + j * 64 + kk);
#pragma unroll
        for (int j = 0; j < 4; j++) {
            acc[j][0] = fmaf(xv[j].x, w0.x, acc[j][0]);
            acc[j][0] = fmaf(xv[j].y, w1.x, acc[j][0]);
            acc[j][1] = fmaf(xv[j].x, w0.y, acc[j][1]);
            acc[j][1] = fmaf(xv[j].y, w1.y, acc[j][1]);
            acc[j][2] = fmaf(xv[j].x, w0.z, acc[j][2]);
            acc[j][2] = fmaf(xv[j].y, w1.z, acc[j][2]);
            acc[j][3] = fmaf(xv[j].x, w0.w, acc[j][3]);
            acc[j][3] = fmaf(xv[j].y, w1.w, acc[j][3]);
        }
    }

    float4 A  = *(const float4*)(corr + b * 64 + cg);
    float4 Dv = *(const float4*)(corr + 512 + b * 64 + cg);
    float4 Bb = *(const float4*)(bias + cg);
    const float sgn = (rh == 0) ? 1.f : -1.f;
    const int bg = q * 8 + b;
    float* op = out + ((size_t)bg * 16384 + (size_t)k * 8 + rh * 4) * 64 + cg;
#pragma unroll
    for (int j = 0; j < 4; j++) {
        float4 rv;
        rv.x = gelu_tanh(acc[j][0] + A.x + sgn * Dv.x + Bb.x);
        rv.y = gelu_tanh(acc[j][1] + A.y + sgn * Dv.y + Bb.y);
        rv.z = gelu_tanh(acc[j][2] + A.z + sgn * Dv.z + Bb.z);
        rv.w = gelu_tanh(acc[j][3] + A.w + sgn * Dv.w + Bb.w);
        *(float4*)(op + j * 64) = rv;
    }
}

extern "C" void kernel_launch(void* const* d_in, const int* in_sizes, int n_in,
                              void* d_out, int out_size) {
    const float* x  = (const float*)d_in[0];   // (32, 16384, 64)
    const float* wA = (const float*)d_in[1];   // (64, 64, 2048)
    const float* wD = (const float*)d_in[2];   // (64, 64, 2048)
    const float* Ws = (const float*)d_in[3];   // (64, 64)
    const float* bs = (const float*)d_in[4];   // (64,)
    float* out = (float*)d_out;

    cudaFuncSetAttribute(fused_kernel,
        cudaFuncAttributeMaxDynamicSharedMemorySize, 41984);

    dim3 tb(32, 8), tg(LC / 32, 4096 / 32, 2);
    transpose_w_kernel<<<tg, tb>>>(wA, wD);

    fused_kernel<<<4 * LC, 256, 41984>>>(x, Ws, bs, out);
}

// round 10
// speedup vs baseline: 1.0105x; 1.0105x over previous
#include <cuda_runtime.h>
#include <cuda_bf16.h>
#include <cstdint>
#include <math.h>

#define LC   2048
#define CINV 0.35355339059327373f   // 1/(2*sqrt(2))

// Transposed wavelet weights, bf16: [which][k][i*64+o]
__device__ __nv_bfloat16 g_wt[2][(size_t)LC * 4096];

__device__ __forceinline__ float gelu_tanh(float v) {
    float z = 0.7978845608028654f * (v + 0.044715f * v * v * v);
    float t;
    asm("tanh.approx.f32 %0, %1;" : "=f"(t) : "f"(z));
    return 0.5f * v * (1.0f + t);
}

// ---------------------------------------------------------------------------
// Kernel 1: transpose w_approx / w_detail (i,o,l) -> (l, i*64+o), f32 -> bf16
// ---------------------------------------------------------------------------
__global__ void transpose_w_kernel(const float* __restrict__ wA,
                                   const float* __restrict__ wD) {
    __shared__ float tile[32][33];
    const float* src = (blockIdx.z == 0) ? wA : wD;
    __nv_bfloat16* dst = g_wt[blockIdx.z];
    int lbase  = blockIdx.x * 32;
    int iobase = blockIdx.y * 32;
    int tx = threadIdx.x, ty = threadIdx.y;   // block (32, 8)
#pragma unroll
    for (int r = 0; r < 32; r += 8)
        tile[ty + r][tx] = src[(size_t)(iobase + ty + r) * LC + (lbase + tx)];
    __syncthreads();
#pragma unroll
    for (int r = 0; r < 32; r += 8)
        dst[(size_t)(lbase + ty + r) * 4096 + (iobase + tx)] =
            __float2bfloat16(tile[tx][ty + r]);
}

// ---------------------------------------------------------------------------
// Kernel 2: fully fused (R8 config + float4 4-kk GEMM inner loop).
// Grid 4096 = (k, half). 256 threads, 16 batches x 8 rows x 64 ch. 3 CTAs/SM.
// shrW dual-use: phase<=2 bf16 W_t (16 KB); phase>=3 f32 (W_skip+I).
// ---------------------------------------------------------------------------
__global__ __launch_bounds__(256, 3) void fused_kernel(
    const float* __restrict__ x, const float* __restrict__ Ws,
    const float* __restrict__ bsk, float* __restrict__ out)
{
    extern __shared__ float sm[];
    float* xs   = sm;            // 16 b * 520 (8x64 + pad 8)   = 8320 fl
    float* shrW = sm + 8320;     // 4096 fl: bf16 W_t [2][4096] then f32 wsk
    float* uv   = sm + 12416;    // [2][64 i][21]               = 2688 fl
    float* corr = sm + 15104;    // [2][16 b][64 o]             = 2048 fl
    float* bias = sm + 17152;    // 64 fl   (total 17216 fl = 68864 B)

    const int k    = blockIdx.x >> 1;
    const int half = blockIdx.x & 1;
    const int tid  = threadIdx.x;

    // ---- Phase 0: loads ----
    const float4* x4  = (const float4*)x;
    float4*       xs4 = (float4*)xs;
#pragma unroll
    for (int it = 0; it < 8; it++) {
        int idx = tid + it * 256;           // 0..2047 float4s
        int bl = idx >> 7, r = idx & 127;
        int b  = half * 16 + bl;
        xs4[bl * 130 + r] = x4[(size_t)b * 262144 + (size_t)k * 128 + r];
    }
    {
        const uint4* wt0 = (const uint4*)(g_wt[0] + (size_t)k * 4096);
        const uint4* wt1 = (const uint4*)(g_wt[1] + (size_t)k * 4096);
        uint4* dstw = (uint4*)shrW;
#pragma unroll
        for (int it = 0; it < 2; it++) {
            int i = tid + it * 256;         // 0..511 uint4 per which
            dstw[i]       = wt0[i];
            dstw[512 + i] = wt1[i];
        }
    }
    if (tid < 64) bias[tid] = bsk[tid];
    __syncthreads();

    // ---- Phase 1: u/v.  p -> (which, b, i); consecutive tid = consecutive i.
    for (int p = tid; p < 2048; p += 256) {
        int i = p & 63, bl = (p >> 6) & 15, which = p >> 10;
        const float* xb = xs + bl * 520 + i;
        float e = 0.f, d = 0.f;
#pragma unroll
        for (int j = 0; j < 4; j++) { e += xb[j * 64]; d += xb[(j + 4) * 64]; }
        uv[which * 1344 + i * 21 + bl] = (which == 0) ? CINV * (e + d)
                                                      : CINV * (e - d);
    }
    __syncthreads();

    // ---- Phase 2: corrections. thread -> (which, b, 8 outputs og..og+7)
    {
        const int which = tid >> 7;
        const int r  = tid & 127;
        const int bl = r >> 3;
        const int og = (r & 7) * 8;
        const __nv_bfloat16* W = (const __nv_bfloat16*)shrW + which * 4096;
        const float* U = uv + which * 1344;

        float acc[8] = {};
#pragma unroll 8
        for (int i = 0; i < 64; i++) {
            float u = U[i * 21 + bl];
            uint4 wv = *(const uint4*)(W + i * 64 + og);
            float2 w0 = __bfloat1622float2(*(const __nv_bfloat162*)&wv.x);
            float2 w1 = __bfloat1622float2(*(const __nv_bfloat162*)&wv.y);
            float2 w2 = __bfloat1622float2(*(const __nv_bfloat162*)&wv.z);
            float2 w3 = __bfloat1622float2(*(const __nv_bfloat162*)&wv.w);
            acc[0] = fmaf(u, w0.x, acc[0]);
            acc[1] = fmaf(u, w0.y, acc[1]);
            acc[2] = fmaf(u, w1.x, acc[2]);
            acc[3] = fmaf(u, w1.y, acc[3]);
            acc[4] = fmaf(u, w2.x, acc[4]);
            acc[5] = fmaf(u, w2.y, acc[5]);
            acc[6] = fmaf(u, w3.x, acc[6]);
            acc[7] = fmaf(u, w3.y, acc[7]);
        }
        float* cp = corr + which * 1024 + bl * 64 + og;
#pragma unroll
        for (int e = 0; e < 8; e++)
            cp[e] = CINV * (acc[e] - U[(og + e) * 21 + bl]);
    }
    __syncthreads();

    // ---- Phase 3: overwrite shrW with (W_skip + I) as f32 ----
#pragma unroll
    for (int it = 0; it < 16; it++) {
        int i = tid + it * 256;             // 0..4095
        float v = Ws[i];
        if ((i >> 6) == (i & 63)) v += 1.0f;
        shrW[i] = v;
    }
    __syncthreads();

    // ---- Phase 4: GEMM + epilogue. 8x4 tile, float4 x loads, 4-kk steps ----
    const int bl = tid >> 4;
    const int cg = (tid & 15) << 2;
    const float* xb = xs + bl * 520;

    float acc[8][4] = {};
#pragma unroll
    for (int kk = 0; kk < 64; kk += 4) {
        float4 w0 = *(const float4*)(shrW + (kk + 0) * 64 + cg);
        float4 w1 = *(const float4*)(shrW + (kk + 1) * 64 + cg);
        float4 w2 = *(const float4*)(shrW + (kk + 2) * 64 + cg);
        float4 w3 = *(const float4*)(shrW + (kk + 3) * 64 + cg);
#pragma unroll
        for (int jh = 0; jh < 2; jh++) {
            float4 xv[4];
#pragma unroll
            for (int j = 0; j < 4; j++)
                xv[j] = *(const float4*)(xb + (jh * 4 + j) * 64 + kk);
#pragma unroll
            for (int j = 0; j < 4; j++) {
                const int jj = jh * 4 + j;
                acc[jj][0] = fmaf(xv[j].x, w0.x, acc[jj][0]);
                acc[jj][0] = fmaf(xv[j].y, w1.x, acc[jj][0]);
                acc[jj][0] = fmaf(xv[j].z, w2.x, acc[jj][0]);
                acc[jj][0] = fmaf(xv[j].w, w3.x, acc[jj][0]);
                acc[jj][1] = fmaf(xv[j].x, w0.y, acc[jj][1]);
                acc[jj][1] = fmaf(xv[j].y, w1.y, acc[jj][1]);
                acc[jj][1] = fmaf(xv[j].z, w2.y, acc[jj][1]);
                acc[jj][1] = fmaf(xv[j].w, w3.y, acc[jj][1]);
                acc[jj][2] = fmaf(xv[j].x, w0.z, acc[jj][2]);
                acc[jj][2] = fmaf(xv[j].y, w1.z, acc[jj][2]);
                acc[jj][2] = fmaf(xv[j].z, w2.z, acc[jj][2]);
                acc[jj][2] = fmaf(xv[j].w, w3.z, acc[jj][2]);
                acc[jj][3] = fmaf(xv[j].x, w0.w, acc[jj][3]);
                acc[jj][3] = fmaf(xv[j].y, w1.w, acc[jj][3]);
                acc[jj][3] = fmaf(xv[j].z, w2.w, acc[jj][3]);
                acc[jj][3] = fmaf(xv[j].w, w3.w, acc[jj][3]);
            }
        }
    }

    float4 A  = *(const float4*)(corr + bl * 64 + cg);
    float4 Dv = *(const float4*)(corr + 1024 + bl * 64 + cg);
    float4 Bb = *(const float4*)(bias + cg);
    const int b = half * 16 + bl;
    float* op = out + ((size_t)b * 16384 + (size_t)k * 8) * 64 + cg;
#pragma unroll
    for (int j = 0; j < 8; j++) {
        float sgn = (j < 4) ? 1.f : -1.f;
        float4 rv;
        rv.x = gelu_tanh(acc[j][0] + A.x + sgn * Dv.x + Bb.x);
        rv.y = gelu_tanh(acc[j][1] + A.y + sgn * Dv.y + Bb.y);
        rv.z = gelu_tanh(acc[j][2] + A.z + sgn * Dv.z + Bb.z);
        rv.w = gelu_tanh(acc[j][3] + A.w + sgn * Dv.w + Bb.w);
        *(float4*)(op + j * 64) = rv;
    }
}

extern "C" void kernel_launch(void* const* d_in, const int* in_sizes, int n_in,
                              void* d_out, int out_size) {
    const float* x  = (const float*)d_in[0];   // (32, 16384, 64)
    const float* wA = (const float*)d_in[1];   // (64, 64, 2048)
    const float* wD = (const float*)d_in[2];   // (64, 64, 2048)
    const float* Ws = (const float*)d_in[3];   // (64, 64)
    const float* bs = (const float*)d_in[4];   // (64,)
    float* out = (float*)d_out;

    cudaFuncSetAttribute(fused_kernel,
        cudaFuncAttributeMaxDynamicSharedMemorySize, 68864);

    dim3 tb(32, 8), tg(LC / 32, 4096 / 32, 2);
    transpose_w_kernel<<<tg, tb>>>(wA, wD);

    fused_kernel<<<2 * LC, 256, 68864>>>(x, Ws, bs, out);
}